// round 1
// baseline (speedup 1.0000x reference)
#include <cuda_runtime.h>
#include <math.h>

#define NB   4
#define NS   2048
#define ND   1024
#define NH   16
#define NDH  64
#define MT   (NB*NS)          // 8192 rows

// ---------------- scratch (device globals: no allocation allowed) ----------
__device__ float g_Q[(size_t)NB*NH*NS*NDH];   // [B,H,S,Dh]
__device__ float g_K[(size_t)NB*NH*NS*NDH];
__device__ float g_V[(size_t)NB*NH*NS*NDH];
__device__ float g_ctx[(size_t)MT*ND];        // [B,S,H*Dh]

// ===========================================================================
// GEMM: C[M,N] = A[M,K] @ W[N,K]^T + bias
// Tile 128x128x16, 256 threads, 8x8 per thread.
// EPI==0: qkv scatter epilogue -> g_Q/g_K/g_V in [B,H,S,Dh]
// EPI==1: plain epilogue -> C (d_out), A taken from g_ctx
// ===========================================================================
template<int EPI>
__global__ __launch_bounds__(256) void gemm_kernel(
    const float* __restrict__ A_in, const float* __restrict__ W,
    const float* __restrict__ bias, float* __restrict__ C,
    int N, int K)
{
    __shared__ float As[16*132];
    __shared__ float Bs[16*132];

    const float* A = (EPI == 1) ? (const float*)g_ctx : A_in;

    const int tid = threadIdx.x;
    const int tx = tid & 15, ty = tid >> 4;
    const int m0 = blockIdx.y * 128, n0 = blockIdx.x * 128;

    float acc[8][8];
    #pragma unroll
    for (int i = 0; i < 8; i++)
        #pragma unroll
        for (int j = 0; j < 8; j++) acc[i][j] = 0.f;

    for (int k0 = 0; k0 < K; k0 += 16) {
        #pragma unroll
        for (int i = 0; i < 2; i++) {
            int idx = tid + i * 256;         // 0..511
            int row = idx >> 2;              // 0..127
            int c4  = (idx & 3) * 4;         // 0,4,8,12
            float4 av = *(const float4*)(A + (size_t)(m0 + row) * K + k0 + c4);
            As[(c4+0)*132 + row] = av.x;
            As[(c4+1)*132 + row] = av.y;
            As[(c4+2)*132 + row] = av.z;
            As[(c4+3)*132 + row] = av.w;
            float4 bv = *(const float4*)(W + (size_t)(n0 + row) * K + k0 + c4);
            Bs[(c4+0)*132 + row] = bv.x;
            Bs[(c4+1)*132 + row] = bv.y;
            Bs[(c4+2)*132 + row] = bv.z;
            Bs[(c4+3)*132 + row] = bv.w;
        }
        __syncthreads();
        #pragma unroll
        for (int kk = 0; kk < 16; kk++) {
            float a[8], b[8];
            *(float4*)&a[0] = *(float4*)&As[kk*132 + ty*8];
            *(float4*)&a[4] = *(float4*)&As[kk*132 + ty*8 + 4];
            *(float4*)&b[0] = *(float4*)&Bs[kk*132 + tx*8];
            *(float4*)&b[4] = *(float4*)&Bs[kk*132 + tx*8 + 4];
            #pragma unroll
            for (int i = 0; i < 8; i++)
                #pragma unroll
                for (int j = 0; j < 8; j++)
                    acc[i][j] += a[i] * b[j];
        }
        __syncthreads();
    }

    // bias for this thread's 8 columns
    float bv[8];
    #pragma unroll
    for (int j = 0; j < 8; j++) bv[j] = bias[n0 + tx*8 + j];

    if (EPI == 0) {
        // n -> (part, h, d). Within a thread's 8 columns part/h are constant
        // (tx*8 block never crosses a 64-wide head boundary).
        int n = n0 + tx * 8;
        int part = n >> 10;
        int rem  = n & 1023;
        int h    = rem >> 6;
        int d    = rem & 63;
        float* dst = (part == 0) ? g_Q : ((part == 1) ? g_K : g_V);
        #pragma unroll
        for (int i = 0; i < 8; i++) {
            int m = m0 + ty*8 + i;
            int b = m >> 11;            // /2048
            int s = m & 2047;
            size_t o = ((((size_t)b * NH + h) * NS) + s) * NDH + d;
            float4 v0 = make_float4(acc[i][0]+bv[0], acc[i][1]+bv[1],
                                    acc[i][2]+bv[2], acc[i][3]+bv[3]);
            float4 v1 = make_float4(acc[i][4]+bv[4], acc[i][5]+bv[5],
                                    acc[i][6]+bv[6], acc[i][7]+bv[7]);
            *(float4*)(dst + o)     = v0;
            *(float4*)(dst + o + 4) = v1;
        }
    } else {
        #pragma unroll
        for (int i = 0; i < 8; i++) {
            int m = m0 + ty*8 + i;
            float4 v0 = make_float4(acc[i][0]+bv[0], acc[i][1]+bv[1],
                                    acc[i][2]+bv[2], acc[i][3]+bv[3]);
            float4 v1 = make_float4(acc[i][4]+bv[4], acc[i][5]+bv[5],
                                    acc[i][6]+bv[6], acc[i][7]+bv[7]);
            *(float4*)(C + (size_t)m * N + n0 + tx*8)     = v0;
            *(float4*)(C + (size_t)m * N + n0 + tx*8 + 4) = v1;
        }
    }
}

// ===========================================================================
// RoPE in place on g_Q, g_K. One thread per (b,h,s,i) pair, i in [0,32).
//   q'[i]    = q[i]*cos(a) + q[i+32]*sin(a)
//   q'[i+32] = q[i+32]*cos(a) - q[i]*sin(a)          (a = pos * 10000^(-i/32))
// ===========================================================================
__global__ void rope_kernel(const int* __restrict__ p)
{
    int idx = blockIdx.x * blockDim.x + threadIdx.x;
    if (idx >= NB*NH*NS*32) return;
    int i = idx & 31;
    int t = idx >> 5;                 // (b*NH+h)*NS + s
    int s = t & (NS - 1);
    int b = t >> 15;                  // / (NH*NS)
    int pos = p[b * NS + s];

    // freq in double to match the fp32-rounded reference value closely
    float f = (float)exp(-(double)i * (9.210340371976184 / 32.0));
    float ang = (float)pos * f;
    float c, sn;
    sincosf(ang, &sn, &c);

    size_t base = (size_t)t * NDH;
    float q1 = g_Q[base + i], q2 = g_Q[base + i + 32];
    g_Q[base + i]      = q1 * c + q2 * sn;
    g_Q[base + i + 32] = q2 * c - q1 * sn;
    float k1 = g_K[base + i], k2 = g_K[base + i + 32];
    g_K[base + i]      = k1 * c + k2 * sn;
    g_K[base + i + 32] = k2 * c - k1 * sn;
}

// ===========================================================================
// Flash-style attention. Block = one (b,h, 64-query tile). 256 threads,
// 4x4 micro-tile (16x16 thread grid). Online softmax over 32 key tiles of 64.
// smem: Qs [d][q] (stride 68), Ks [d][key] (stride 68, reused as Ps[key][q]),
//       Vs [key][d] (stride 64). Inner loops are LDS.128 + FFMA only.
// ===========================================================================
#define QS_STR 68
#define KS_STR 68
#define VS_STR 64
#define SMEM_ATTN ((64*QS_STR + 64*KS_STR + 64*VS_STR) * 4)   // 51200 B

__global__ __launch_bounds__(256) void attn_kernel()
{
    extern __shared__ float sm[];
    float* Qs = sm;
    float* Ks = Qs + 64 * QS_STR;
    float* Vs = Ks + 64 * KS_STR;

    const int tid = threadIdx.x;
    const int tx = tid & 15, ty = tid >> 4;
    const int qt = blockIdx.x, bh = blockIdx.y;

    const float* Qg = g_Q + ((size_t)bh * NS + qt * 64) * NDH;
    const float* Kg = g_K + (size_t)bh * NS * NDH;
    const float* Vg = g_V + (size_t)bh * NS * NDH;

    // load Q tile, transposed to [d][q], pre-scaled by 1/sqrt(64)
    #pragma unroll
    for (int i = 0; i < 4; i++) {
        int idx = tid + i * 256;
        int r  = idx >> 4;           // query 0..63
        int c4 = (idx & 15) * 4;     // dim 0..60
        float4 v = *(const float4*)(Qg + r * NDH + c4);
        Qs[(c4+0)*QS_STR + r] = v.x * 0.125f;
        Qs[(c4+1)*QS_STR + r] = v.y * 0.125f;
        Qs[(c4+2)*QS_STR + r] = v.z * 0.125f;
        Qs[(c4+3)*QS_STR + r] = v.w * 0.125f;
    }

    float acc[4][4];
    float m_run[4], l_run[4];
    #pragma unroll
    for (int r = 0; r < 4; r++) {
        m_run[r] = -INFINITY; l_run[r] = 0.f;
        #pragma unroll
        for (int c = 0; c < 4; c++) acc[r][c] = 0.f;
    }
    __syncthreads();

    for (int kt = 0; kt < NS / 64; kt++) {
        const float* Kt = Kg + (size_t)kt * 64 * NDH;
        const float* Vt = Vg + (size_t)kt * 64 * NDH;
        #pragma unroll
        for (int i = 0; i < 4; i++) {
            int idx = tid + i * 256;
            int r  = idx >> 4;
            int c4 = (idx & 15) * 4;
            float4 kv = *(const float4*)(Kt + r * NDH + c4);
            Ks[(c4+0)*KS_STR + r] = kv.x;
            Ks[(c4+1)*KS_STR + r] = kv.y;
            Ks[(c4+2)*KS_STR + r] = kv.z;
            Ks[(c4+3)*KS_STR + r] = kv.w;
            float4 vv = *(const float4*)(Vt + r * NDH + c4);
            *(float4*)&Vs[r * VS_STR + c4] = vv;
        }
        __syncthreads();

        // S = Q K^T (scaled)
        float s[4][4];
        #pragma unroll
        for (int r = 0; r < 4; r++)
            #pragma unroll
            for (int c = 0; c < 4; c++) s[r][c] = 0.f;
        #pragma unroll 8
        for (int kk = 0; kk < 64; kk++) {
            float4 qv = *(float4*)&Qs[kk * QS_STR + ty * 4];
            float4 kv = *(float4*)&Ks[kk * KS_STR + tx * 4];
            float qa[4] = {qv.x, qv.y, qv.z, qv.w};
            float ka[4] = {kv.x, kv.y, kv.z, kv.w};
            #pragma unroll
            for (int r = 0; r < 4; r++)
                #pragma unroll
                for (int c = 0; c < 4; c++)
                    s[r][c] += qa[r] * ka[c];
        }

        // online softmax update (row stats shared across the 16-thread tx group)
        #pragma unroll
        for (int r = 0; r < 4; r++) {
            float rmax = fmaxf(fmaxf(s[r][0], s[r][1]), fmaxf(s[r][2], s[r][3]));
            #pragma unroll
            for (int off = 8; off >= 1; off >>= 1)
                rmax = fmaxf(rmax, __shfl_xor_sync(0xffffffffu, rmax, off));
            float nm = fmaxf(m_run[r], rmax);
            float alpha = __expf(m_run[r] - nm);
            m_run[r] = nm;
            float rsum = 0.f;
            #pragma unroll
            for (int c = 0; c < 4; c++) {
                s[r][c] = __expf(s[r][c] - nm);
                rsum += s[r][c];
            }
            #pragma unroll
            for (int off = 8; off >= 1; off >>= 1)
                rsum += __shfl_xor_sync(0xffffffffu, rsum, off);
            l_run[r] = l_run[r] * alpha + rsum;
            #pragma unroll
            for (int c = 0; c < 4; c++) acc[r][c] *= alpha;
        }
        __syncthreads();   // all threads done reading Ks

        // write P transposed into Ks: Ps[key][q]
        #pragma unroll
        for (int c = 0; c < 4; c++)
            #pragma unroll
            for (int r = 0; r < 4; r++)
                Ks[(tx*4 + c) * KS_STR + ty*4 + r] = s[r][c];
        __syncthreads();

        // O += P V
        #pragma unroll 8
        for (int kk = 0; kk < 64; kk++) {
            float4 pv = *(float4*)&Ks[kk * KS_STR + ty * 4];
            float4 vv = *(float4*)&Vs[kk * VS_STR + tx * 4];
            float pa[4] = {pv.x, pv.y, pv.z, pv.w};
            float va[4] = {vv.x, vv.y, vv.z, vv.w};
            #pragma unroll
            for (int r = 0; r < 4; r++)
                #pragma unroll
                for (int c = 0; c < 4; c++)
                    acc[r][c] += pa[r] * va[c];
        }
        __syncthreads();   // before next K/V tile overwrites smem
    }

    // epilogue: O /= l, write ctx in [B,S,H*Dh]
    int b = bh >> 4, h = bh & 15;
    #pragma unroll
    for (int r = 0; r < 4; r++) {
        float inv = 1.0f / l_run[r];
        int q = qt * 64 + ty * 4 + r;
        float4 o = make_float4(acc[r][0]*inv, acc[r][1]*inv,
                               acc[r][2]*inv, acc[r][3]*inv);
        *(float4*)(g_ctx + ((size_t)b * NS + q) * ND + h * NDH + tx * 4) = o;
    }
}

// ===========================================================================
extern "C" void kernel_launch(void* const* d_in, const int* in_sizes, int n_in,
                              void* d_out, int out_size)
{
    (void)in_sizes; (void)n_in; (void)out_size;
    const float* x      = (const float*)d_in[0];
    const int*   p      = (const int*)d_in[1];
    const float* Wqkv_w = (const float*)d_in[2];
    const float* Wqkv_b = (const float*)d_in[3];
    const float* Wo_w   = (const float*)d_in[4];
    const float* Wo_b   = (const float*)d_in[5];
    float* out = (float*)d_out;

    cudaFuncSetAttribute(attn_kernel,
                         cudaFuncAttributeMaxDynamicSharedMemorySize, SMEM_ATTN);

    // 1) QKV projection + bias, scattered into Q/K/V [B,H,S,Dh]
    dim3 g1(3 * ND / 128, MT / 128);     // 24 x 64
    gemm_kernel<0><<<g1, 256>>>(x, Wqkv_w, Wqkv_b, nullptr, 3 * ND, ND);

    // 2) RoPE on Q and K
    int nrope = NB * NH * NS * 32;
    rope_kernel<<<(nrope + 255) / 256, 256>>>(p);

    // 3) Attention -> g_ctx [B,S,H*Dh]
    attn_kernel<<<dim3(NS / 64, NB * NH), 256, SMEM_ATTN>>>();

    // 4) Output projection + bias -> d_out
    dim3 g2(ND / 128, MT / 128);         // 8 x 64
    gemm_kernel<1><<<g2, 256>>>(nullptr, Wo_w, Wo_b, out, ND, ND);
}

// round 3
// speedup vs baseline: 1.3465x; 1.3465x over previous
#include <cuda_runtime.h>
#include <cuda_bf16.h>
#include <math.h>
#include <stdint.h>

#define NB   4
#define NS   2048
#define ND   1024
#define NH   16
#define NDH  64
#define MT   (NB*NS)          // 8192 rows

// ---------------- scratch (device globals: no allocation allowed) ----------
__device__ float g_Q[(size_t)NB*NH*NS*NDH];   // [B,H,S,Dh]
__device__ float g_K[(size_t)NB*NH*NS*NDH];
__device__ float g_V[(size_t)NB*NH*NS*NDH];
__device__ float g_ctx[(size_t)MT*ND];        // [B,S,H*Dh]

// ======================= mma helpers =======================================
__device__ __forceinline__ uint32_t smem_u32(const void* p) {
    uint32_t a;
    asm("{ .reg .u64 t; cvta.to.shared.u64 t, %1; cvt.u32.u64 %0, t; }"
        : "=r"(a) : "l"(p));
    return a;
}
__device__ __forceinline__ void ldmx4(uint32_t addr, uint32_t r[4]) {
    asm volatile("ldmatrix.sync.aligned.m8n8.x4.shared.b16 {%0,%1,%2,%3}, [%4];"
                 : "=r"(r[0]), "=r"(r[1]), "=r"(r[2]), "=r"(r[3]) : "r"(addr));
}
__device__ __forceinline__ void mma16816(float c[4], const uint32_t a[4],
                                         uint32_t b0, uint32_t b1) {
    asm volatile(
        "mma.sync.aligned.m16n8k16.row.col.f32.bf16.bf16.f32 "
        "{%0,%1,%2,%3}, {%4,%5,%6,%7}, {%8,%9}, {%0,%1,%2,%3};"
        : "+f"(c[0]), "+f"(c[1]), "+f"(c[2]), "+f"(c[3])
        : "r"(a[0]), "r"(a[1]), "r"(a[2]), "r"(a[3]), "r"(b0), "r"(b1));
}
// split 8 fp32 into 8 bf16 hi + 8 bf16 lo (4 packed words each)
__device__ __forceinline__ void split8(float4 v0, float4 v1,
                                       uint32_t hi[4], uint32_t lo[4]) {
    float x[8] = {v0.x, v0.y, v0.z, v0.w, v1.x, v1.y, v1.z, v1.w};
    #pragma unroll
    for (int i = 0; i < 4; i++) {
        __nv_bfloat162 h = __floats2bfloat162_rn(x[2*i], x[2*i+1]);
        hi[i] = *(uint32_t*)&h;
        float r0 = x[2*i]   - __bfloat162float(h.x);
        float r1 = x[2*i+1] - __bfloat162float(h.y);
        __nv_bfloat162 l = __floats2bfloat162_rn(r0, r1);
        lo[i] = *(uint32_t*)&l;
    }
}
// XOR swizzle: 16B chunk c (0..3) of 64B row
__device__ __forceinline__ uint32_t swz(int row, int c) {
    return (uint32_t)(row * 64 + ((c ^ ((row >> 1) & 3)) * 16));
}

// ===========================================================================
// 3xBF16 mma GEMM: C[M,N] = A[M,K] @ W[N,K]^T + bias
// CTA tile 128x128, K staged by 32. smem/stage: Ahi|Alo|Whi|Wlo (4 x 8KB),
// double buffered (64KB). 8 warps: 4(m) x 2(n); warp tile 32x64.
// EPI==0: QKV scatter epilogue -> g_Q/g_K/g_V in [B,H,S,Dh]
// EPI==1: plain epilogue -> C (d_out), A taken from g_ctx
// ===========================================================================
#define STG_BYTES 32768
#define GK_SMEM   (2*STG_BYTES)

template<int EPI>
__global__ __launch_bounds__(256, 1) void gemm_mma(
    const float* __restrict__ A_in, const float* __restrict__ W,
    const float* __restrict__ bias, float* __restrict__ C,
    int N, int K)
{
    extern __shared__ char smc[];
    const uint32_t sb = smem_u32(smc);
    const float* A = (EPI == 1) ? (const float*)g_ctx : A_in;

    const int tid  = threadIdx.x;
    const int warp = tid >> 5, lane = tid & 31;
    const int wm = warp & 3, cg = warp >> 2;
    const int m0 = blockIdx.y * 128, n0 = blockIdx.x * 128;

    // ------- per-thread load geometry (constant across stages) -------------
    const int rowL = tid >> 2;          // 0..63  (second chunk is rowL+64)
    const int cL   = tid & 3;           // 16B chunk in row
    const float* aP0 = A + (size_t)(m0 + rowL) * K + cL * 8;
    const float* aP1 = aP0 + (size_t)64 * K;
    const float* wP0 = W + (size_t)(n0 + rowL) * K + cL * 8;
    const float* wP1 = wP0 + (size_t)64 * K;
    const uint32_t off0 = swz(rowL, cL);
    const uint32_t off1 = swz(rowL + 64, cL);

    float acc[2][8][4];
    #pragma unroll
    for (int mt = 0; mt < 2; mt++)
        #pragma unroll
        for (int nt = 0; nt < 8; nt++)
            #pragma unroll
            for (int i = 0; i < 4; i++) acc[mt][nt][i] = 0.f;

    // ------- ldmatrix addresses (constant across stages, per buffer) -------
    // A frags: rows wm*32 + mt*16 + (lane&15), chunk h*2 + (lane>>4)
    // B frags: rows cg*64 + ntp*16 + (lane&7) + ((lane>>4)&1)*8, chunk h*2 + ((lane>>3)&1)
    uint32_t aOff[2][2], bOff[2][4];    // [h][mt], [h][ntp]
    #pragma unroll
    for (int h = 0; h < 2; h++) {
        #pragma unroll
        for (int mt = 0; mt < 2; mt++) {
            int r = wm * 32 + mt * 16 + (lane & 15);
            int c = h * 2 + ((lane >> 4) & 1);
            aOff[h][mt] = swz(r, c);
        }
        #pragma unroll
        for (int ntp = 0; ntp < 4; ntp++) {
            int r = cg * 64 + ntp * 16 + (lane & 7) + ((lane >> 4) & 1) * 8;
            int c = h * 2 + ((lane >> 3) & 1);
            bOff[h][ntp] = swz(r, c);
        }
    }

    const int NSTG = K / 32;

    // ------- prologue: fill stage 0 ----------------------------------------
    {
        float4 a00 = *(const float4*)(aP0);     float4 a01 = *(const float4*)(aP0 + 4);
        float4 a10 = *(const float4*)(aP1);     float4 a11 = *(const float4*)(aP1 + 4);
        float4 w00 = *(const float4*)(wP0);     float4 w01 = *(const float4*)(wP0 + 4);
        float4 w10 = *(const float4*)(wP1);     float4 w11 = *(const float4*)(wP1 + 4);
        uint32_t h4[4], l4[4];
        split8(a00, a01, h4, l4);
        *(uint4*)(smc + off0)        = *(uint4*)h4;
        *(uint4*)(smc + 8192 + off0) = *(uint4*)l4;
        split8(a10, a11, h4, l4);
        *(uint4*)(smc + off1)        = *(uint4*)h4;
        *(uint4*)(smc + 8192 + off1) = *(uint4*)l4;
        split8(w00, w01, h4, l4);
        *(uint4*)(smc + 16384 + off0) = *(uint4*)h4;
        *(uint4*)(smc + 24576 + off0) = *(uint4*)l4;
        split8(w10, w11, h4, l4);
        *(uint4*)(smc + 16384 + off1) = *(uint4*)h4;
        *(uint4*)(smc + 24576 + off1) = *(uint4*)l4;
    }
    __syncthreads();

    for (int s = 0; s < NSTG; s++) {
        const int buf = s & 1;
        const uint32_t base = sb + buf * STG_BYTES;

        // prefetch next stage gmem -> regs
        float4 a00, a01, a10, a11, w00, w01, w10, w11;
        if (s + 1 < NSTG) {
            const int ko = (s + 1) * 32;
            a00 = *(const float4*)(aP0 + ko); a01 = *(const float4*)(aP0 + ko + 4);
            a10 = *(const float4*)(aP1 + ko); a11 = *(const float4*)(aP1 + ko + 4);
            w00 = *(const float4*)(wP0 + ko); w01 = *(const float4*)(wP0 + ko + 4);
            w10 = *(const float4*)(wP1 + ko); w11 = *(const float4*)(wP1 + ko + 4);
        }

        // compute current stage: 2 k16 halves
        #pragma unroll
        for (int h = 0; h < 2; h++) {
            uint32_t ah[2][4], al[2][4];
            #pragma unroll
            for (int mt = 0; mt < 2; mt++) {
                ldmx4(base + aOff[h][mt], ah[mt]);
                ldmx4(base + 8192 + aOff[h][mt], al[mt]);
            }
            #pragma unroll
            for (int ntp = 0; ntp < 4; ntp++) {
                uint32_t bh[4], bl[4];
                ldmx4(base + 16384 + bOff[h][ntp], bh);
                ldmx4(base + 24576 + bOff[h][ntp], bl);
                #pragma unroll
                for (int mt = 0; mt < 2; mt++) {
                    mma16816(acc[mt][2*ntp],   ah[mt], bh[0], bh[1]);
                    mma16816(acc[mt][2*ntp+1], ah[mt], bh[2], bh[3]);
                    mma16816(acc[mt][2*ntp],   ah[mt], bl[0], bl[1]);
                    mma16816(acc[mt][2*ntp+1], ah[mt], bl[2], bl[3]);
                    mma16816(acc[mt][2*ntp],   al[mt], bh[0], bh[1]);
                    mma16816(acc[mt][2*ntp+1], al[mt], bh[2], bh[3]);
                }
            }
        }

        // store next stage into other buffer
        if (s + 1 < NSTG) {
            char* nb = smc + (buf ^ 1) * STG_BYTES;
            uint32_t h4[4], l4[4];
            split8(a00, a01, h4, l4);
            *(uint4*)(nb + off0)        = *(uint4*)h4;
            *(uint4*)(nb + 8192 + off0) = *(uint4*)l4;
            split8(a10, a11, h4, l4);
            *(uint4*)(nb + off1)        = *(uint4*)h4;
            *(uint4*)(nb + 8192 + off1) = *(uint4*)l4;
            split8(w00, w01, h4, l4);
            *(uint4*)(nb + 16384 + off0) = *(uint4*)h4;
            *(uint4*)(nb + 24576 + off0) = *(uint4*)l4;
            split8(w10, w11, h4, l4);
            *(uint4*)(nb + 16384 + off1) = *(uint4*)h4;
            *(uint4*)(nb + 24576 + off1) = *(uint4*)l4;
        }
        __syncthreads();
    }

    // ---------------- epilogue ---------------------------------------------
    const int g = lane >> 2, tig = lane & 3;
    const int nBase = n0 + cg * 64;

    float bcol[8][2];
    #pragma unroll
    for (int nt = 0; nt < 8; nt++) {
        bcol[nt][0] = bias[nBase + nt * 8 + tig * 2];
        bcol[nt][1] = bias[nBase + nt * 8 + tig * 2 + 1];
    }

    if (EPI == 0) {
        int part = nBase >> 10;
        int hd   = (nBase & 1023) >> 6;
        float* dst = (part == 0) ? g_Q : ((part == 1) ? g_K : g_V);
        #pragma unroll
        for (int mt = 0; mt < 2; mt++)
            #pragma unroll
            for (int half = 0; half < 2; half++) {
                int m = m0 + wm * 32 + mt * 16 + g + half * 8;
                int b = m >> 11, sq = m & 2047;
                size_t rb = (((size_t)b * NH + hd) * NS + sq) * NDH;
                #pragma unroll
                for (int nt = 0; nt < 8; nt++) {
                    int d = nt * 8 + tig * 2;
                    float2 v;
                    v.x = acc[mt][nt][half*2]   + bcol[nt][0];
                    v.y = acc[mt][nt][half*2+1] + bcol[nt][1];
                    *(float2*)(dst + rb + d) = v;
                }
            }
    } else {
        #pragma unroll
        for (int mt = 0; mt < 2; mt++)
            #pragma unroll
            for (int half = 0; half < 2; half++) {
                int m = m0 + wm * 32 + mt * 16 + g + half * 8;
                #pragma unroll
                for (int nt = 0; nt < 8; nt++) {
                    int n = nBase + nt * 8 + tig * 2;
                    float2 v;
                    v.x = acc[mt][nt][half*2]   + bcol[nt][0];
                    v.y = acc[mt][nt][half*2+1] + bcol[nt][1];
                    *(float2*)(C + (size_t)m * N + n) = v;
                }
            }
    }
}

// ===========================================================================
// RoPE in place on g_Q, g_K. One thread per (b,h,s,i) pair, i in [0,32).
// ===========================================================================
__global__ void rope_kernel(const int* __restrict__ p)
{
    int idx = blockIdx.x * blockDim.x + threadIdx.x;
    if (idx >= NB*NH*NS*32) return;
    int i = idx & 31;
    int t = idx >> 5;                 // (b*NH+h)*NS + s
    int s = t & (NS - 1);
    int b = t >> 15;                  // / (NH*NS)
    int pos = p[b * NS + s];

    float f = (float)exp(-(double)i * (9.210340371976184 / 32.0));
    float ang = (float)pos * f;
    float c, sn;
    sincosf(ang, &sn, &c);

    size_t base = (size_t)t * NDH;
    float q1 = g_Q[base + i], q2 = g_Q[base + i + 32];
    g_Q[base + i]      = q1 * c + q2 * sn;
    g_Q[base + i + 32] = q2 * c - q1 * sn;
    float k1 = g_K[base + i], k2 = g_K[base + i + 32];
    g_K[base + i]      = k1 * c + k2 * sn;
    g_K[base + i + 32] = k2 * c - k1 * sn;
}

// ===========================================================================
// Flash-style attention (SIMT, unchanged from passing R1 version).
// ===========================================================================
#define QS_STR 68
#define KS_STR 68
#define VS_STR 64
#define SMEM_ATTN ((64*QS_STR + 64*KS_STR + 64*VS_STR) * 4)   // 51200 B

__global__ __launch_bounds__(256) void attn_kernel()
{
    extern __shared__ float sm[];
    float* Qs = sm;
    float* Ks = Qs + 64 * QS_STR;
    float* Vs = Ks + 64 * KS_STR;

    const int tid = threadIdx.x;
    const int tx = tid & 15, ty = tid >> 4;
    const int qt = blockIdx.x, bh = blockIdx.y;

    const float* Qg = g_Q + ((size_t)bh * NS + qt * 64) * NDH;
    const float* Kg = g_K + (size_t)bh * NS * NDH;
    const float* Vg = g_V + (size_t)bh * NS * NDH;

    #pragma unroll
    for (int i = 0; i < 4; i++) {
        int idx = tid + i * 256;
        int r  = idx >> 4;
        int c4 = (idx & 15) * 4;
        float4 v = *(const float4*)(Qg + r * NDH + c4);
        Qs[(c4+0)*QS_STR + r] = v.x * 0.125f;
        Qs[(c4+1)*QS_STR + r] = v.y * 0.125f;
        Qs[(c4+2)*QS_STR + r] = v.z * 0.125f;
        Qs[(c4+3)*QS_STR + r] = v.w * 0.125f;
    }

    float acc[4][4];
    float m_run[4], l_run[4];
    #pragma unroll
    for (int r = 0; r < 4; r++) {
        m_run[r] = -INFINITY; l_run[r] = 0.f;
        #pragma unroll
        for (int c = 0; c < 4; c++) acc[r][c] = 0.f;
    }
    __syncthreads();

    for (int kt = 0; kt < NS / 64; kt++) {
        const float* Kt = Kg + (size_t)kt * 64 * NDH;
        const float* Vt = Vg + (size_t)kt * 64 * NDH;
        #pragma unroll
        for (int i = 0; i < 4; i++) {
            int idx = tid + i * 256;
            int r  = idx >> 4;
            int c4 = (idx & 15) * 4;
            float4 kv = *(const float4*)(Kt + r * NDH + c4);
            Ks[(c4+0)*KS_STR + r] = kv.x;
            Ks[(c4+1)*KS_STR + r] = kv.y;
            Ks[(c4+2)*KS_STR + r] = kv.z;
            Ks[(c4+3)*KS_STR + r] = kv.w;
            float4 vv = *(const float4*)(Vt + r * NDH + c4);
            *(float4*)&Vs[r * VS_STR + c4] = vv;
        }
        __syncthreads();

        float s[4][4];
        #pragma unroll
        for (int r = 0; r < 4; r++)
            #pragma unroll
            for (int c = 0; c < 4; c++) s[r][c] = 0.f;
        #pragma unroll 8
        for (int kk = 0; kk < 64; kk++) {
            float4 qv = *(float4*)&Qs[kk * QS_STR + ty * 4];
            float4 kv = *(float4*)&Ks[kk * KS_STR + tx * 4];
            float qa[4] = {qv.x, qv.y, qv.z, qv.w};
            float ka[4] = {kv.x, kv.y, kv.z, kv.w};
            #pragma unroll
            for (int r = 0; r < 4; r++)
                #pragma unroll
                for (int c = 0; c < 4; c++)
                    s[r][c] += qa[r] * ka[c];
        }

        #pragma unroll
        for (int r = 0; r < 4; r++) {
            float rmax = fmaxf(fmaxf(s[r][0], s[r][1]), fmaxf(s[r][2], s[r][3]));
            #pragma unroll
            for (int off = 8; off >= 1; off >>= 1)
                rmax = fmaxf(rmax, __shfl_xor_sync(0xffffffffu, rmax, off));
            float nm = fmaxf(m_run[r], rmax);
            float alpha = __expf(m_run[r] - nm);
            m_run[r] = nm;
            float rsum = 0.f;
            #pragma unroll
            for (int c = 0; c < 4; c++) {
                s[r][c] = __expf(s[r][c] - nm);
                rsum += s[r][c];
            }
            #pragma unroll
            for (int off = 8; off >= 1; off >>= 1)
                rsum += __shfl_xor_sync(0xffffffffu, rsum, off);
            l_run[r] = l_run[r] * alpha + rsum;
            #pragma unroll
            for (int c = 0; c < 4; c++) acc[r][c] *= alpha;
        }
        __syncthreads();

        #pragma unroll
        for (int c = 0; c < 4; c++)
            #pragma unroll
            for (int r = 0; r < 4; r++)
                Ks[(tx*4 + c) * KS_STR + ty*4 + r] = s[r][c];
        __syncthreads();

        #pragma unroll 8
        for (int kk = 0; kk < 64; kk++) {
            float4 pv = *(float4*)&Ks[kk * KS_STR + ty * 4];
            float4 vv = *(float4*)&Vs[kk * VS_STR + tx * 4];
            float pa[4] = {pv.x, pv.y, pv.z, pv.w};
            float va[4] = {vv.x, vv.y, vv.z, vv.w};
            #pragma unroll
            for (int r = 0; r < 4; r++)
                #pragma unroll
                for (int c = 0; c < 4; c++)
                    acc[r][c] += pa[r] * va[c];
        }
        __syncthreads();
    }

    int b = bh >> 4, h = bh & 15;
    #pragma unroll
    for (int r = 0; r < 4; r++) {
        float inv = 1.0f / l_run[r];
        int q = qt * 64 + ty * 4 + r;
        float4 o = make_float4(acc[r][0]*inv, acc[r][1]*inv,
                               acc[r][2]*inv, acc[r][3]*inv);
        *(float4*)(g_ctx + ((size_t)b * NS + q) * ND + h * NDH + tx * 4) = o;
    }
}

// ===========================================================================
extern "C" void kernel_launch(void* const* d_in, const int* in_sizes, int n_in,
                              void* d_out, int out_size)
{
    (void)in_sizes; (void)n_in; (void)out_size;
    const float* x      = (const float*)d_in[0];
    const int*   p      = (const int*)d_in[1];
    const float* Wqkv_w = (const float*)d_in[2];
    const float* Wqkv_b = (const float*)d_in[3];
    const float* Wo_w   = (const float*)d_in[4];
    const float* Wo_b   = (const float*)d_in[5];
    float* out = (float*)d_out;

    cudaFuncSetAttribute(gemm_mma<0>,
                         cudaFuncAttributeMaxDynamicSharedMemorySize, GK_SMEM);
    cudaFuncSetAttribute(gemm_mma<1>,
                         cudaFuncAttributeMaxDynamicSharedMemorySize, GK_SMEM);
    cudaFuncSetAttribute(attn_kernel,
                         cudaFuncAttributeMaxDynamicSharedMemorySize, SMEM_ATTN);

    // 1) QKV projection + bias, scattered into Q/K/V [B,H,S,Dh]
    dim3 g1(3 * ND / 128, MT / 128);     // 24 x 64
    gemm_mma<0><<<g1, 256, GK_SMEM>>>(x, Wqkv_w, Wqkv_b, nullptr, 3 * ND, ND);

    // 2) RoPE on Q and K
    int nrope = NB * NH * NS * 32;
    rope_kernel<<<(nrope + 255) / 256, 256>>>(p);

    // 3) Attention -> g_ctx [B,S,H*Dh]
    attn_kernel<<<dim3(NS / 64, NB * NH), 256, SMEM_ATTN>>>();

    // 4) Output projection + bias -> d_out
    dim3 g2(ND / 128, MT / 128);         // 8 x 64
    gemm_mma<1><<<g2, 256, GK_SMEM>>>(nullptr, Wo_w, Wo_b, out, ND, ND);
}

// round 4
// speedup vs baseline: 2.9012x; 2.1547x over previous
#include <cuda_runtime.h>
#include <cuda_bf16.h>
#include <math.h>
#include <stdint.h>

#define NB   4
#define NS   2048
#define ND   1024
#define NH   16
#define NDH  64
#define MT   (NB*NS)          // 8192 rows

// ---------------- scratch (device globals: no allocation allowed) ----------
__device__ float g_Q[(size_t)NB*NH*NS*NDH];   // [B,H,S,Dh]
__device__ float g_K[(size_t)NB*NH*NS*NDH];
__device__ float g_V[(size_t)NB*NH*NS*NDH];
__device__ float g_ctx[(size_t)MT*ND];        // [B,S,H*Dh]

// ======================= mma helpers =======================================
__device__ __forceinline__ uint32_t smem_u32(const void* p) {
    uint32_t a;
    asm("{ .reg .u64 t; cvta.to.shared.u64 t, %1; cvt.u32.u64 %0, t; }"
        : "=r"(a) : "l"(p));
    return a;
}
__device__ __forceinline__ void ldmx4(uint32_t addr, uint32_t r[4]) {
    asm volatile("ldmatrix.sync.aligned.m8n8.x4.shared.b16 {%0,%1,%2,%3}, [%4];"
                 : "=r"(r[0]), "=r"(r[1]), "=r"(r[2]), "=r"(r[3]) : "r"(addr));
}
__device__ __forceinline__ void ldmx4t(uint32_t addr, uint32_t r[4]) {
    asm volatile("ldmatrix.sync.aligned.m8n8.x4.trans.shared.b16 {%0,%1,%2,%3}, [%4];"
                 : "=r"(r[0]), "=r"(r[1]), "=r"(r[2]), "=r"(r[3]) : "r"(addr));
}
__device__ __forceinline__ void mma16816(float c[4], const uint32_t a[4],
                                         uint32_t b0, uint32_t b1) {
    asm volatile(
        "mma.sync.aligned.m16n8k16.row.col.f32.bf16.bf16.f32 "
        "{%0,%1,%2,%3}, {%4,%5,%6,%7}, {%8,%9}, {%0,%1,%2,%3};"
        : "+f"(c[0]), "+f"(c[1]), "+f"(c[2]), "+f"(c[3])
        : "r"(a[0]), "r"(a[1]), "r"(a[2]), "r"(a[3]), "r"(b0), "r"(b1));
}
// split 8 fp32 into 8 bf16 hi + 8 bf16 lo (4 packed words each)
__device__ __forceinline__ void split8(float4 v0, float4 v1,
                                       uint32_t hi[4], uint32_t lo[4]) {
    float x[8] = {v0.x, v0.y, v0.z, v0.w, v1.x, v1.y, v1.z, v1.w};
    #pragma unroll
    for (int i = 0; i < 4; i++) {
        __nv_bfloat162 h = __floats2bfloat162_rn(x[2*i], x[2*i+1]);
        hi[i] = *(uint32_t*)&h;
        float r0 = x[2*i]   - __bfloat162float(h.x);
        float r1 = x[2*i+1] - __bfloat162float(h.y);
        __nv_bfloat162 l = __floats2bfloat162_rn(r0, r1);
        lo[i] = *(uint32_t*)&l;
    }
}
__device__ __forceinline__ void split2(float x, float y, uint32_t& hi, uint32_t& lo) {
    __nv_bfloat162 h = __floats2bfloat162_rn(x, y);
    hi = *(uint32_t*)&h;
    __nv_bfloat162 l = __floats2bfloat162_rn(x - __bfloat162float(h.x),
                                             y - __bfloat162float(h.y));
    lo = *(uint32_t*)&l;
}
// XOR swizzle: 16B chunk c (0..3) of 64B row
__device__ __forceinline__ uint32_t swz(int row, int c) {
    return (uint32_t)(row * 64 + ((c ^ ((row >> 1) & 3)) * 16));
}
// XOR swizzle for 128B rows: chunk c (0..7)
__device__ __forceinline__ uint32_t swz128(int row, int c) {
    return (uint32_t)(row * 128 + ((c ^ (row & 7)) * 16));
}

// ===========================================================================
// 3xBF16 mma GEMM: C[M,N] = A[M,K] @ W[N,K]^T + bias  (validated R3 kernel)
// ===========================================================================
#define STG_BYTES 32768
#define GK_SMEM   (2*STG_BYTES)

template<int EPI>
__global__ __launch_bounds__(256, 1) void gemm_mma(
    const float* __restrict__ A_in, const float* __restrict__ W,
    const float* __restrict__ bias, float* __restrict__ C,
    int N, int K)
{
    extern __shared__ char smc[];
    const uint32_t sb = smem_u32(smc);
    const float* A = (EPI == 1) ? (const float*)g_ctx : A_in;

    const int tid  = threadIdx.x;
    const int warp = tid >> 5, lane = tid & 31;
    const int wm = warp & 3, cg = warp >> 2;
    const int m0 = blockIdx.y * 128, n0 = blockIdx.x * 128;

    const int rowL = tid >> 2;
    const int cL   = tid & 3;
    const float* aP0 = A + (size_t)(m0 + rowL) * K + cL * 8;
    const float* aP1 = aP0 + (size_t)64 * K;
    const float* wP0 = W + (size_t)(n0 + rowL) * K + cL * 8;
    const float* wP1 = wP0 + (size_t)64 * K;
    const uint32_t off0 = swz(rowL, cL);
    const uint32_t off1 = swz(rowL + 64, cL);

    float acc[2][8][4];
    #pragma unroll
    for (int mt = 0; mt < 2; mt++)
        #pragma unroll
        for (int nt = 0; nt < 8; nt++)
            #pragma unroll
            for (int i = 0; i < 4; i++) acc[mt][nt][i] = 0.f;

    uint32_t aOff[2][2], bOff[2][4];
    #pragma unroll
    for (int h = 0; h < 2; h++) {
        #pragma unroll
        for (int mt = 0; mt < 2; mt++) {
            int r = wm * 32 + mt * 16 + (lane & 15);
            int c = h * 2 + ((lane >> 4) & 1);
            aOff[h][mt] = swz(r, c);
        }
        #pragma unroll
        for (int ntp = 0; ntp < 4; ntp++) {
            int r = cg * 64 + ntp * 16 + (lane & 7) + ((lane >> 4) & 1) * 8;
            int c = h * 2 + ((lane >> 3) & 1);
            bOff[h][ntp] = swz(r, c);
        }
    }

    const int NSTG = K / 32;

    {
        float4 a00 = *(const float4*)(aP0);     float4 a01 = *(const float4*)(aP0 + 4);
        float4 a10 = *(const float4*)(aP1);     float4 a11 = *(const float4*)(aP1 + 4);
        float4 w00 = *(const float4*)(wP0);     float4 w01 = *(const float4*)(wP0 + 4);
        float4 w10 = *(const float4*)(wP1);     float4 w11 = *(const float4*)(wP1 + 4);
        uint32_t h4[4], l4[4];
        split8(a00, a01, h4, l4);
        *(uint4*)(smc + off0)        = *(uint4*)h4;
        *(uint4*)(smc + 8192 + off0) = *(uint4*)l4;
        split8(a10, a11, h4, l4);
        *(uint4*)(smc + off1)        = *(uint4*)h4;
        *(uint4*)(smc + 8192 + off1) = *(uint4*)l4;
        split8(w00, w01, h4, l4);
        *(uint4*)(smc + 16384 + off0) = *(uint4*)h4;
        *(uint4*)(smc + 24576 + off0) = *(uint4*)l4;
        split8(w10, w11, h4, l4);
        *(uint4*)(smc + 16384 + off1) = *(uint4*)h4;
        *(uint4*)(smc + 24576 + off1) = *(uint4*)l4;
    }
    __syncthreads();

    for (int s = 0; s < NSTG; s++) {
        const int buf = s & 1;
        const uint32_t base = sb + buf * STG_BYTES;

        float4 a00, a01, a10, a11, w00, w01, w10, w11;
        if (s + 1 < NSTG) {
            const int ko = (s + 1) * 32;
            a00 = *(const float4*)(aP0 + ko); a01 = *(const float4*)(aP0 + ko + 4);
            a10 = *(const float4*)(aP1 + ko); a11 = *(const float4*)(aP1 + ko + 4);
            w00 = *(const float4*)(wP0 + ko); w01 = *(const float4*)(wP0 + ko + 4);
            w10 = *(const float4*)(wP1 + ko); w11 = *(const float4*)(wP1 + ko + 4);
        }

        #pragma unroll
        for (int h = 0; h < 2; h++) {
            uint32_t ah[2][4], al[2][4];
            #pragma unroll
            for (int mt = 0; mt < 2; mt++) {
                ldmx4(base + aOff[h][mt], ah[mt]);
                ldmx4(base + 8192 + aOff[h][mt], al[mt]);
            }
            #pragma unroll
            for (int ntp = 0; ntp < 4; ntp++) {
                uint32_t bh[4], bl[4];
                ldmx4(base + 16384 + bOff[h][ntp], bh);
                ldmx4(base + 24576 + bOff[h][ntp], bl);
                #pragma unroll
                for (int mt = 0; mt < 2; mt++) {
                    mma16816(acc[mt][2*ntp],   ah[mt], bh[0], bh[1]);
                    mma16816(acc[mt][2*ntp+1], ah[mt], bh[2], bh[3]);
                    mma16816(acc[mt][2*ntp],   ah[mt], bl[0], bl[1]);
                    mma16816(acc[mt][2*ntp+1], ah[mt], bl[2], bl[3]);
                    mma16816(acc[mt][2*ntp],   al[mt], bh[0], bh[1]);
                    mma16816(acc[mt][2*ntp+1], al[mt], bh[2], bh[3]);
                }
            }
        }

        if (s + 1 < NSTG) {
            char* nb = smc + (buf ^ 1) * STG_BYTES;
            uint32_t h4[4], l4[4];
            split8(a00, a01, h4, l4);
            *(uint4*)(nb + off0)        = *(uint4*)h4;
            *(uint4*)(nb + 8192 + off0) = *(uint4*)l4;
            split8(a10, a11, h4, l4);
            *(uint4*)(nb + off1)        = *(uint4*)h4;
            *(uint4*)(nb + 8192 + off1) = *(uint4*)l4;
            split8(w00, w01, h4, l4);
            *(uint4*)(nb + 16384 + off0) = *(uint4*)h4;
            *(uint4*)(nb + 24576 + off0) = *(uint4*)l4;
            split8(w10, w11, h4, l4);
            *(uint4*)(nb + 16384 + off1) = *(uint4*)h4;
            *(uint4*)(nb + 24576 + off1) = *(uint4*)l4;
        }
        __syncthreads();
    }

    const int g = lane >> 2, tig = lane & 3;
    const int nBase = n0 + cg * 64;

    float bcol[8][2];
    #pragma unroll
    for (int nt = 0; nt < 8; nt++) {
        bcol[nt][0] = bias[nBase + nt * 8 + tig * 2];
        bcol[nt][1] = bias[nBase + nt * 8 + tig * 2 + 1];
    }

    if (EPI == 0) {
        int part = nBase >> 10;
        int hd   = (nBase & 1023) >> 6;
        float* dst = (part == 0) ? g_Q : ((part == 1) ? g_K : g_V);
        #pragma unroll
        for (int mt = 0; mt < 2; mt++)
            #pragma unroll
            for (int half = 0; half < 2; half++) {
                int m = m0 + wm * 32 + mt * 16 + g + half * 8;
                int b = m >> 11, sq = m & 2047;
                size_t rb = (((size_t)b * NH + hd) * NS + sq) * NDH;
                #pragma unroll
                for (int nt = 0; nt < 8; nt++) {
                    int d = nt * 8 + tig * 2;
                    float2 v;
                    v.x = acc[mt][nt][half*2]   + bcol[nt][0];
                    v.y = acc[mt][nt][half*2+1] + bcol[nt][1];
                    *(float2*)(dst + rb + d) = v;
                }
            }
    } else {
        #pragma unroll
        for (int mt = 0; mt < 2; mt++)
            #pragma unroll
            for (int half = 0; half < 2; half++) {
                int m = m0 + wm * 32 + mt * 16 + g + half * 8;
                #pragma unroll
                for (int nt = 0; nt < 8; nt++) {
                    int n = nBase + nt * 8 + tig * 2;
                    float2 v;
                    v.x = acc[mt][nt][half*2]   + bcol[nt][0];
                    v.y = acc[mt][nt][half*2+1] + bcol[nt][1];
                    *(float2*)(C + (size_t)m * N + n) = v;
                }
            }
    }
}

// ===========================================================================
// RoPE in place on g_Q, g_K.
// ===========================================================================
__global__ void rope_kernel(const int* __restrict__ p)
{
    int idx = blockIdx.x * blockDim.x + threadIdx.x;
    if (idx >= NB*NH*NS*32) return;
    int i = idx & 31;
    int t = idx >> 5;
    int s = t & (NS - 1);
    int b = t >> 15;
    int pos = p[b * NS + s];

    float f = (float)exp(-(double)i * (9.210340371976184 / 32.0));
    float ang = (float)pos * f;
    float c, sn;
    sincosf(ang, &sn, &c);

    size_t base = (size_t)t * NDH;
    float q1 = g_Q[base + i], q2 = g_Q[base + i + 32];
    g_Q[base + i]      = q1 * c + q2 * sn;
    g_Q[base + i + 32] = q2 * c - q1 * sn;
    float k1 = g_K[base + i], k2 = g_K[base + i + 32];
    g_K[base + i]      = k1 * c + k2 * sn;
    g_K[base + i + 32] = k2 * c - k1 * sn;
}

// ===========================================================================
// Tensor-core flash attention (3xBF16 split on QK^T and PV).
// Block = 128 queries of one (b,h). 4 warps, each 32 q. 64-key tiles.
// smem (64KB): Qh 0 | Ql 16K | Kh 32K | Kl 40K | Vh 48K | Vl 56K
//   Q: 128 rows x 128B (64 bf16), swizzled.  K/V: 64 rows x 128B.
// ===========================================================================
#define AQ_H 0
#define AQ_L 16384
#define AK_H 32768
#define AK_L 40960
#define AV_H 49152
#define AV_L 57344
#define AT_SMEM 65536

__global__ __launch_bounds__(128, 2) void attn_mma()
{
    extern __shared__ char sma[];
    const uint32_t sb = smem_u32(sma);

    const int tid = threadIdx.x;
    const int warp = tid >> 5, lane = tid & 31;
    const int qt = blockIdx.x, bh = blockIdx.y;

    const float* Qg = g_Q + ((size_t)bh * NS + qt * 128) * NDH;
    const float* Kg = g_K + (size_t)bh * NS * NDH;
    const float* Vg = g_V + (size_t)bh * NS * NDH;

    // ---- fill Q (scaled by 1/8), split hi/lo, swizzled 128B rows ----------
    #pragma unroll
    for (int i = 0; i < 8; i++) {
        int f8 = tid + i * 128;           // 0..1023
        int row = f8 >> 3, c = f8 & 7;
        float4 v0 = *(const float4*)(Qg + row * NDH + c * 8);
        float4 v1 = *(const float4*)(Qg + row * NDH + c * 8 + 4);
        v0.x *= 0.125f; v0.y *= 0.125f; v0.z *= 0.125f; v0.w *= 0.125f;
        v1.x *= 0.125f; v1.y *= 0.125f; v1.z *= 0.125f; v1.w *= 0.125f;
        uint32_t h4[4], l4[4];
        split8(v0, v1, h4, l4);
        uint32_t o = swz128(row, c);
        *(uint4*)(sma + AQ_H + o) = *(uint4*)h4;
        *(uint4*)(sma + AQ_L + o) = *(uint4*)l4;
    }

    // ---- fragment smem offsets (fixed per thread) -------------------------
    uint32_t qOff[4][2][2];   // [kc][mt][hi/lo base added later] -> offset only
    #pragma unroll
    for (int kc = 0; kc < 4; kc++)
        #pragma unroll
        for (int mt = 0; mt < 2; mt++) {
            int r = warp * 32 + mt * 16 + (lane & 15);
            int c = kc * 2 + ((lane >> 4) & 1);
            qOff[kc][mt] [0]= swz128(r, c);   // store once; same for hi/lo regions
            qOff[kc][mt][1] = qOff[kc][mt][0];
        }
    uint32_t kOff[4][4];      // [kc][ntp]
    #pragma unroll
    for (int kc = 0; kc < 4; kc++)
        #pragma unroll
        for (int ntp = 0; ntp < 4; ntp++) {
            int r = ntp * 16 + (lane & 7) + ((lane >> 4) & 1) * 8;
            int c = kc * 2 + ((lane >> 3) & 1);
            kOff[kc][ntp] = swz128(r, c);
        }
    uint32_t vOff[4][4];      // [kq][dp]  (trans loads)
    #pragma unroll
    for (int kq = 0; kq < 4; kq++)
        #pragma unroll
        for (int dp = 0; dp < 4; dp++) {
            int r = kq * 16 + (lane & 7) + ((lane >> 3) & 1) * 8;
            int c = dp * 2 + ((lane >> 4) & 1);
            vOff[kq][dp] = swz128(r, c);
        }

    float Oa[2][8][4];
    float mrun[2][2], lrun[2][2];
    #pragma unroll
    for (int mt = 0; mt < 2; mt++) {
        mrun[mt][0] = -INFINITY; mrun[mt][1] = -INFINITY;
        lrun[mt][0] = 0.f;       lrun[mt][1] = 0.f;
        #pragma unroll
        for (int dt = 0; dt < 8; dt++)
            #pragma unroll
            for (int i = 0; i < 4; i++) Oa[mt][dt][i] = 0.f;
    }
    __syncthreads();

    for (int kt = 0; kt < NS / 64; kt++) {
        const float* Kt = Kg + (size_t)kt * 64 * NDH;
        const float* Vt = Vg + (size_t)kt * 64 * NDH;

        // ---- fill K and V tiles (split hi/lo) -----------------------------
        #pragma unroll
        for (int i = 0; i < 4; i++) {
            int f8 = tid + i * 128;       // 0..511
            int row = f8 >> 3, c = f8 & 7;
            uint32_t o = swz128(row, c);
            float4 k0 = *(const float4*)(Kt + row * NDH + c * 8);
            float4 k1 = *(const float4*)(Kt + row * NDH + c * 8 + 4);
            uint32_t h4[4], l4[4];
            split8(k0, k1, h4, l4);
            *(uint4*)(sma + AK_H + o) = *(uint4*)h4;
            *(uint4*)(sma + AK_L + o) = *(uint4*)l4;
            float4 v0 = *(const float4*)(Vt + row * NDH + c * 8);
            float4 v1 = *(const float4*)(Vt + row * NDH + c * 8 + 4);
            split8(v0, v1, h4, l4);
            *(uint4*)(sma + AV_H + o) = *(uint4*)h4;
            *(uint4*)(sma + AV_L + o) = *(uint4*)l4;
        }
        __syncthreads();

        // ---- S = Q K^T (3-term split) -------------------------------------
        float S[2][8][4];
        #pragma unroll
        for (int mt = 0; mt < 2; mt++)
            #pragma unroll
            for (int nt = 0; nt < 8; nt++)
                #pragma unroll
                for (int i = 0; i < 4; i++) S[mt][nt][i] = 0.f;

        #pragma unroll
        for (int kc = 0; kc < 4; kc++) {
            uint32_t qh[2][4], ql[2][4];
            #pragma unroll
            for (int mt = 0; mt < 2; mt++) {
                ldmx4(sb + AQ_H + qOff[kc][mt][0], qh[mt]);
                ldmx4(sb + AQ_L + qOff[kc][mt][0], ql[mt]);
            }
            #pragma unroll
            for (int ntp = 0; ntp < 4; ntp++) {
                uint32_t kh[4], kl[4];
                ldmx4(sb + AK_H + kOff[kc][ntp], kh);
                ldmx4(sb + AK_L + kOff[kc][ntp], kl);
                #pragma unroll
                for (int mt = 0; mt < 2; mt++) {
                    mma16816(S[mt][2*ntp],   qh[mt], kh[0], kh[1]);
                    mma16816(S[mt][2*ntp+1], qh[mt], kh[2], kh[3]);
                    mma16816(S[mt][2*ntp],   qh[mt], kl[0], kl[1]);
                    mma16816(S[mt][2*ntp+1], qh[mt], kl[2], kl[3]);
                    mma16816(S[mt][2*ntp],   ql[mt], kh[0], kh[1]);
                    mma16816(S[mt][2*ntp+1], ql[mt], kh[2], kh[3]);
                }
            }
        }

        // ---- online softmax -----------------------------------------------
        #pragma unroll
        for (int mt = 0; mt < 2; mt++) {
            float mx0 = -INFINITY, mx1 = -INFINITY;
            #pragma unroll
            for (int j = 0; j < 8; j++) {
                mx0 = fmaxf(mx0, fmaxf(S[mt][j][0], S[mt][j][1]));
                mx1 = fmaxf(mx1, fmaxf(S[mt][j][2], S[mt][j][3]));
            }
            mx0 = fmaxf(mx0, __shfl_xor_sync(0xffffffffu, mx0, 1));
            mx0 = fmaxf(mx0, __shfl_xor_sync(0xffffffffu, mx0, 2));
            mx1 = fmaxf(mx1, __shfl_xor_sync(0xffffffffu, mx1, 1));
            mx1 = fmaxf(mx1, __shfl_xor_sync(0xffffffffu, mx1, 2));
            float nm0 = fmaxf(mrun[mt][0], mx0);
            float nm1 = fmaxf(mrun[mt][1], mx1);
            float a0 = __expf(mrun[mt][0] - nm0);
            float a1 = __expf(mrun[mt][1] - nm1);
            mrun[mt][0] = nm0; mrun[mt][1] = nm1;
            float s0 = 0.f, s1 = 0.f;
            #pragma unroll
            for (int j = 0; j < 8; j++) {
                S[mt][j][0] = __expf(S[mt][j][0] - nm0); s0 += S[mt][j][0];
                S[mt][j][1] = __expf(S[mt][j][1] - nm0); s0 += S[mt][j][1];
                S[mt][j][2] = __expf(S[mt][j][2] - nm1); s1 += S[mt][j][2];
                S[mt][j][3] = __expf(S[mt][j][3] - nm1); s1 += S[mt][j][3];
            }
            s0 += __shfl_xor_sync(0xffffffffu, s0, 1);
            s0 += __shfl_xor_sync(0xffffffffu, s0, 2);
            s1 += __shfl_xor_sync(0xffffffffu, s1, 1);
            s1 += __shfl_xor_sync(0xffffffffu, s1, 2);
            lrun[mt][0] = lrun[mt][0] * a0 + s0;
            lrun[mt][1] = lrun[mt][1] * a1 + s1;
            #pragma unroll
            for (int dt = 0; dt < 8; dt++) {
                Oa[mt][dt][0] *= a0; Oa[mt][dt][1] *= a0;
                Oa[mt][dt][2] *= a1; Oa[mt][dt][3] *= a1;
            }
        }

        // ---- O += P V (3-term split; P repacked from S regs) --------------
        #pragma unroll
        for (int kq = 0; kq < 4; kq++) {
            uint32_t pah[2][4], pal[2][4];
            #pragma unroll
            for (int mt = 0; mt < 2; mt++) {
                split2(S[mt][2*kq][0],   S[mt][2*kq][1],   pah[mt][0], pal[mt][0]);
                split2(S[mt][2*kq][2],   S[mt][2*kq][3],   pah[mt][1], pal[mt][1]);
                split2(S[mt][2*kq+1][0], S[mt][2*kq+1][1], pah[mt][2], pal[mt][2]);
                split2(S[mt][2*kq+1][2], S[mt][2*kq+1][3], pah[mt][3], pal[mt][3]);
            }
            #pragma unroll
            for (int dp = 0; dp < 4; dp++) {
                uint32_t vh[4], vl[4];
                ldmx4t(sb + AV_H + vOff[kq][dp], vh);
                ldmx4t(sb + AV_L + vOff[kq][dp], vl);
                #pragma unroll
                for (int mt = 0; mt < 2; mt++) {
                    mma16816(Oa[mt][2*dp],   pah[mt], vh[0], vh[1]);
                    mma16816(Oa[mt][2*dp+1], pah[mt], vh[2], vh[3]);
                    mma16816(Oa[mt][2*dp],   pah[mt], vl[0], vl[1]);
                    mma16816(Oa[mt][2*dp+1], pah[mt], vl[2], vl[3]);
                    mma16816(Oa[mt][2*dp],   pal[mt], vh[0], vh[1]);
                    mma16816(Oa[mt][2*dp+1], pal[mt], vh[2], vh[3]);
                }
            }
        }
        __syncthreads();
    }

    // ---- epilogue: O /= l -> g_ctx [B,S,H*Dh] -----------------------------
    const int b = bh >> 4, h = bh & 15;
    const int g = lane >> 2, tg = lane & 3;
    #pragma unroll
    for (int mt = 0; mt < 2; mt++)
        #pragma unroll
        for (int half = 0; half < 2; half++) {
            int q = qt * 128 + warp * 32 + mt * 16 + g + half * 8;
            float inv = 1.0f / lrun[mt][half];
            #pragma unroll
            for (int dt = 0; dt < 8; dt++) {
                float2 v;
                v.x = Oa[mt][dt][half*2]   * inv;
                v.y = Oa[mt][dt][half*2+1] * inv;
                *(float2*)(g_ctx + ((size_t)b * NS + q) * ND + h * NDH
                           + dt * 8 + tg * 2) = v;
            }
        }
}

// ===========================================================================
extern "C" void kernel_launch(void* const* d_in, const int* in_sizes, int n_in,
                              void* d_out, int out_size)
{
    (void)in_sizes; (void)n_in; (void)out_size;
    const float* x      = (const float*)d_in[0];
    const int*   p      = (const int*)d_in[1];
    const float* Wqkv_w = (const float*)d_in[2];
    const float* Wqkv_b = (const float*)d_in[3];
    const float* Wo_w   = (const float*)d_in[4];
    const float* Wo_b   = (const float*)d_in[5];
    float* out = (float*)d_out;

    cudaFuncSetAttribute(gemm_mma<0>,
                         cudaFuncAttributeMaxDynamicSharedMemorySize, GK_SMEM);
    cudaFuncSetAttribute(gemm_mma<1>,
                         cudaFuncAttributeMaxDynamicSharedMemorySize, GK_SMEM);
    cudaFuncSetAttribute(attn_mma,
                         cudaFuncAttributeMaxDynamicSharedMemorySize, AT_SMEM);

    dim3 g1(3 * ND / 128, MT / 128);
    gemm_mma<0><<<g1, 256, GK_SMEM>>>(x, Wqkv_w, Wqkv_b, nullptr, 3 * ND, ND);

    int nrope = NB * NH * NS * 32;
    rope_kernel<<<(nrope + 255) / 256, 256>>>(p);

    attn_mma<<<dim3(NS / 128, NB * NH), 128, AT_SMEM>>>();

    dim3 g2(ND / 128, MT / 128);
    gemm_mma<1><<<g2, 256, GK_SMEM>>>(nullptr, Wo_w, Wo_b, out, ND, ND);
}

// round 5
// speedup vs baseline: 3.1615x; 1.0897x over previous
#include <cuda_runtime.h>
#include <cuda_bf16.h>
#include <math.h>
#include <stdint.h>

#define NB   4
#define NS   2048
#define ND   1024
#define NH   16
#define NDH  64
#define MT   (NB*NS)          // 8192 rows
#define QKV_ELEMS ((size_t)NB*NH*NS*NDH)

// ---------------- scratch (device globals: no allocation allowed) ----------
__device__ float g_Q[QKV_ELEMS];              // fp32 pre-RoPE
__device__ float g_K[QKV_ELEMS];
__device__ __nv_bfloat16 g_Qh[QKV_ELEMS], g_Ql[QKV_ELEMS];   // post-RoPE, *0.125
__device__ __nv_bfloat16 g_Kh[QKV_ELEMS], g_Kl[QKV_ELEMS];
__device__ __nv_bfloat16 g_Vh[QKV_ELEMS], g_Vl[QKV_ELEMS];
__device__ __nv_bfloat16 g_xh[(size_t)MT*ND],   g_xl[(size_t)MT*ND];
__device__ __nv_bfloat16 g_wqh[(size_t)3*ND*ND], g_wql[(size_t)3*ND*ND];
__device__ __nv_bfloat16 g_woh[(size_t)ND*ND],  g_wol[(size_t)ND*ND];
__device__ __nv_bfloat16 g_ctxh[(size_t)MT*ND], g_ctxl[(size_t)MT*ND];

// ======================= helpers ===========================================
__device__ __forceinline__ uint32_t smem_u32(const void* p) {
    uint32_t a;
    asm("{ .reg .u64 t; cvta.to.shared.u64 t, %1; cvt.u32.u64 %0, t; }"
        : "=r"(a) : "l"(p));
    return a;
}
__device__ __forceinline__ void ldmx4(uint32_t addr, uint32_t r[4]) {
    asm volatile("ldmatrix.sync.aligned.m8n8.x4.shared.b16 {%0,%1,%2,%3}, [%4];"
                 : "=r"(r[0]), "=r"(r[1]), "=r"(r[2]), "=r"(r[3]) : "r"(addr));
}
__device__ __forceinline__ void ldmx4t(uint32_t addr, uint32_t r[4]) {
    asm volatile("ldmatrix.sync.aligned.m8n8.x4.trans.shared.b16 {%0,%1,%2,%3}, [%4];"
                 : "=r"(r[0]), "=r"(r[1]), "=r"(r[2]), "=r"(r[3]) : "r"(addr));
}
__device__ __forceinline__ void mma16816(float c[4], const uint32_t a[4],
                                         uint32_t b0, uint32_t b1) {
    asm volatile(
        "mma.sync.aligned.m16n8k16.row.col.f32.bf16.bf16.f32 "
        "{%0,%1,%2,%3}, {%4,%5,%6,%7}, {%8,%9}, {%0,%1,%2,%3};"
        : "+f"(c[0]), "+f"(c[1]), "+f"(c[2]), "+f"(c[3])
        : "r"(a[0]), "r"(a[1]), "r"(a[2]), "r"(a[3]), "r"(b0), "r"(b1));
}
__device__ __forceinline__ void split2(float x, float y, uint32_t& hi, uint32_t& lo) {
    __nv_bfloat162 h = __floats2bfloat162_rn(x, y);
    hi = *(uint32_t*)&h;
    __nv_bfloat162 l = __floats2bfloat162_rn(x - __bfloat162float(h.x),
                                             y - __bfloat162float(h.y));
    lo = *(uint32_t*)&l;
}
// XOR swizzle: 16B chunk c of 64B row
__device__ __forceinline__ uint32_t swz(int row, int c) {
    return (uint32_t)(row * 64 + ((c ^ ((row >> 1) & 3)) * 16));
}
// XOR swizzle for 128B rows
__device__ __forceinline__ uint32_t swz128(int row, int c) {
    return (uint32_t)(row * 128 + ((c ^ (row & 7)) * 16));
}
__device__ __forceinline__ void cpa16(uint32_t dst, const void* src) {
    asm volatile("cp.async.cg.shared.global [%0], [%1], 16;"
                 :: "r"(dst), "l"(src));
}
#define CP_COMMIT()  asm volatile("cp.async.commit_group;")
#define CP_WAIT(n)   asm volatile("cp.async.wait_group %0;" :: "n"(n))

// ===========================================================================
// split fp32 array into bf16 hi/lo
// ===========================================================================
__global__ void conv_split(const float4* __restrict__ in,
                           uint2* __restrict__ hi, uint2* __restrict__ lo, int n4)
{
    int i = blockIdx.x * blockDim.x + threadIdx.x;
    if (i >= n4) return;
    float4 v = in[i];
    uint32_t h0, l0, h1, l1;
    split2(v.x, v.y, h0, l0);
    split2(v.z, v.w, h1, l1);
    hi[i] = make_uint2(h0, h1);
    lo[i] = make_uint2(l0, l1);
}

// ===========================================================================
// bf16 3-term GEMM with pre-split operands + cp.async 4-stage pipeline.
// C[M,N] = (Ah+Al)[M,K] @ (Wh+Wl)[N,K]^T + bias  (3 of 4 product terms)
// CTA tile 128x128, K-chunk 32. Stage 32KB: Ah|Al|Wh|Wl (8KB each, 64B rows).
// EPI==0: QKV epilogue (Q,K fp32; V split bf16).  EPI==1: fp32 C.
// ===========================================================================
#define GSTG 32768
#define GK_SMEM (4*GSTG)

template<int EPI>
__global__ __launch_bounds__(256, 1) void gemm_bf16(
    const __nv_bfloat16* __restrict__ Ah, const __nv_bfloat16* __restrict__ Al,
    const __nv_bfloat16* __restrict__ Wh, const __nv_bfloat16* __restrict__ Wl,
    const float* __restrict__ bias, float* __restrict__ C, int N, int K)
{
    extern __shared__ char smc[];
    const uint32_t sb = smem_u32(smc);

    const int tid  = threadIdx.x;
    const int warp = tid >> 5, lane = tid & 31;
    const int wm = warp & 3, cg = warp >> 2;
    const int m0 = blockIdx.y * 128, n0 = blockIdx.x * 128;

    // load geometry: 2 chunks/thread/array
    const int rowA = tid >> 2, cA = tid & 3;          // chunk idx tid
    const int rowB = (tid + 256) >> 2, cB = tid & 3;  // chunk idx tid+256
    const uint32_t offA = swz(rowA, cA), offB = swz(rowB, cB);
    const __nv_bfloat16* pAhA = Ah + (size_t)(m0 + rowA) * K + cA * 8;
    const __nv_bfloat16* pAlA = Al + (size_t)(m0 + rowA) * K + cA * 8;
    const __nv_bfloat16* pWhA = Wh + (size_t)(n0 + rowA) * K + cA * 8;
    const __nv_bfloat16* pWlA = Wl + (size_t)(n0 + rowA) * K + cA * 8;
    const __nv_bfloat16* pAhB = Ah + (size_t)(m0 + rowB) * K + cB * 8;
    const __nv_bfloat16* pAlB = Al + (size_t)(m0 + rowB) * K + cB * 8;
    const __nv_bfloat16* pWhB = Wh + (size_t)(n0 + rowB) * K + cB * 8;
    const __nv_bfloat16* pWlB = Wl + (size_t)(n0 + rowB) * K + cB * 8;

    float acc[2][8][4];
    #pragma unroll
    for (int mt = 0; mt < 2; mt++)
        #pragma unroll
        for (int nt = 0; nt < 8; nt++)
            #pragma unroll
            for (int i = 0; i < 4; i++) acc[mt][nt][i] = 0.f;

    uint32_t aOff[2][2], bOff[2][4];
    #pragma unroll
    for (int h = 0; h < 2; h++) {
        #pragma unroll
        for (int mt = 0; mt < 2; mt++) {
            int r = wm * 32 + mt * 16 + (lane & 15);
            int c = h * 2 + ((lane >> 4) & 1);
            aOff[h][mt] = swz(r, c);
        }
        #pragma unroll
        for (int ntp = 0; ntp < 4; ntp++) {
            int r = cg * 64 + ntp * 16 + (lane & 7) + ((lane >> 4) & 1) * 8;
            int c = h * 2 + ((lane >> 3) & 1);
            bOff[h][ntp] = swz(r, c);
        }
    }

    const int NSTG = K / 32;

    auto issue = [&](int s) {
        const uint32_t base = sb + (s & 3) * GSTG;
        const int k0 = s * 32;
        cpa16(base + offA,         pAhA + k0);
        cpa16(base + 8192  + offA, pAlA + k0);
        cpa16(base + 16384 + offA, pWhA + k0);
        cpa16(base + 24576 + offA, pWlA + k0);
        cpa16(base + offB,         pAhB + k0);
        cpa16(base + 8192  + offB, pAlB + k0);
        cpa16(base + 16384 + offB, pWhB + k0);
        cpa16(base + 24576 + offB, pWlB + k0);
    };

    issue(0); CP_COMMIT();
    issue(1); CP_COMMIT();
    issue(2); CP_COMMIT();

    for (int s = 0; s < NSTG; s++) {
        CP_WAIT(2);
        __syncthreads();
        if (s + 3 < NSTG) issue(s + 3);
        CP_COMMIT();

        const uint32_t base = sb + (s & 3) * GSTG;
        #pragma unroll
        for (int h = 0; h < 2; h++) {
            uint32_t ah[2][4], al[2][4];
            #pragma unroll
            for (int mt = 0; mt < 2; mt++) {
                ldmx4(base + aOff[h][mt], ah[mt]);
                ldmx4(base + 8192 + aOff[h][mt], al[mt]);
            }
            #pragma unroll
            for (int ntp = 0; ntp < 4; ntp++) {
                uint32_t bh[4], bl[4];
                ldmx4(base + 16384 + bOff[h][ntp], bh);
                ldmx4(base + 24576 + bOff[h][ntp], bl);
                #pragma unroll
                for (int mt = 0; mt < 2; mt++) {
                    mma16816(acc[mt][2*ntp],   ah[mt], bh[0], bh[1]);
                    mma16816(acc[mt][2*ntp+1], ah[mt], bh[2], bh[3]);
                    mma16816(acc[mt][2*ntp],   ah[mt], bl[0], bl[1]);
                    mma16816(acc[mt][2*ntp+1], ah[mt], bl[2], bl[3]);
                    mma16816(acc[mt][2*ntp],   al[mt], bh[0], bh[1]);
                    mma16816(acc[mt][2*ntp+1], al[mt], bh[2], bh[3]);
                }
            }
        }
    }

    // ---------------- epilogue ---------------------------------------------
    const int g = lane >> 2, tig = lane & 3;
    const int nBase = n0 + cg * 64;

    float bcol[8][2];
    #pragma unroll
    for (int nt = 0; nt < 8; nt++) {
        bcol[nt][0] = bias[nBase + nt * 8 + tig * 2];
        bcol[nt][1] = bias[nBase + nt * 8 + tig * 2 + 1];
    }

    if (EPI == 0) {
        int part = nBase >> 10;
        int hd   = (nBase & 1023) >> 6;
        #pragma unroll
        for (int mt = 0; mt < 2; mt++)
            #pragma unroll
            for (int half = 0; half < 2; half++) {
                int m = m0 + wm * 32 + mt * 16 + g + half * 8;
                int b = m >> 11, sq = m & 2047;
                size_t rb = (((size_t)b * NH + hd) * NS + sq) * NDH;
                if (part < 2) {
                    float* dst = part ? g_K : g_Q;
                    #pragma unroll
                    for (int nt = 0; nt < 8; nt++) {
                        int d = nt * 8 + tig * 2;
                        float2 v;
                        v.x = acc[mt][nt][half*2]   + bcol[nt][0];
                        v.y = acc[mt][nt][half*2+1] + bcol[nt][1];
                        *(float2*)(dst + rb + d) = v;
                    }
                } else {
                    #pragma unroll
                    for (int nt = 0; nt < 8; nt++) {
                        int d = nt * 8 + tig * 2;
                        float vx = acc[mt][nt][half*2]   + bcol[nt][0];
                        float vy = acc[mt][nt][half*2+1] + bcol[nt][1];
                        uint32_t hi, lo;
                        split2(vx, vy, hi, lo);
                        *(uint32_t*)((char*)g_Vh + (rb + d) * 2) = hi;
                        *(uint32_t*)((char*)g_Vl + (rb + d) * 2) = lo;
                    }
                }
            }
    } else {
        #pragma unroll
        for (int mt = 0; mt < 2; mt++)
            #pragma unroll
            for (int half = 0; half < 2; half++) {
                int m = m0 + wm * 32 + mt * 16 + g + half * 8;
                #pragma unroll
                for (int nt = 0; nt < 8; nt++) {
                    int n = nBase + nt * 8 + tig * 2;
                    float2 v;
                    v.x = acc[mt][nt][half*2]   + bcol[nt][0];
                    v.y = acc[mt][nt][half*2+1] + bcol[nt][1];
                    *(float2*)(C + (size_t)m * N + n) = v;
                }
            }
    }
}

// ===========================================================================
// RoPE: read fp32 Q/K, rotate, write bf16 hi/lo (Q pre-scaled by 0.125).
// ===========================================================================
__global__ void rope_split(const int* __restrict__ p)
{
    int idx = blockIdx.x * blockDim.x + threadIdx.x;
    if (idx >= NB*NH*NS*32) return;
    int i = idx & 31;
    int t = idx >> 5;
    int s = t & (NS - 1);
    int b = t >> 15;
    int pos = p[b * NS + s];

    float f = (float)exp(-(double)i * (9.210340371976184 / 32.0));
    float ang = (float)pos * f;
    float c, sn;
    sincosf(ang, &sn, &c);

    size_t base = (size_t)t * NDH;
    float q1 = g_Q[base + i], q2 = g_Q[base + i + 32];
    float rq1 = (q1 * c + q2 * sn) * 0.125f;
    float rq2 = (q2 * c - q1 * sn) * 0.125f;
    float k1 = g_K[base + i], k2 = g_K[base + i + 32];
    float rk1 = k1 * c + k2 * sn;
    float rk2 = k2 * c - k1 * sn;

    __nv_bfloat16 h;
    h = __float2bfloat16_rn(rq1);
    g_Qh[base + i] = h;      g_Ql[base + i]      = __float2bfloat16_rn(rq1 - __bfloat162float(h));
    h = __float2bfloat16_rn(rq2);
    g_Qh[base + i + 32] = h; g_Ql[base + i + 32] = __float2bfloat16_rn(rq2 - __bfloat162float(h));
    h = __float2bfloat16_rn(rk1);
    g_Kh[base + i] = h;      g_Kl[base + i]      = __float2bfloat16_rn(rk1 - __bfloat162float(h));
    h = __float2bfloat16_rn(rk2);
    g_Kh[base + i + 32] = h; g_Kl[base + i + 32] = __float2bfloat16_rn(rk2 - __bfloat162float(h));
}

// ===========================================================================
// Tensor-core flash attention, pre-split bf16 operands, cp.async K/V stages.
// Block = 128 q of one (b,h). smem: Qh 0 |Ql 16K| 2 stages @32K: Kh|Kl|Vh|Vl.
// ===========================================================================
#define AQ_H 0
#define AQ_L 16384
#define ASTG_BASE 32768
#define ASTG 32768
#define AT_SMEM (ASTG_BASE + 2*ASTG)    // 98304

__global__ __launch_bounds__(128, 2) void attn_mma()
{
    extern __shared__ char sma[];
    const uint32_t sb = smem_u32(sma);

    const int tid = threadIdx.x;
    const int warp = tid >> 5, lane = tid & 31;
    const int qt = blockIdx.x, bh = blockIdx.y;

    const size_t qbase  = ((size_t)bh * NS + qt * 128) * NDH;
    const size_t kvbase = (size_t)bh * NS * NDH;

    // ---- issue Q fill (cp.async) ------------------------------------------
    {
        #pragma unroll
        for (int j = 0; j < 8; j++) {
            int idx = tid + j * 128;        // 0..1023
            int row = idx >> 3, c = idx & 7;
            uint32_t o = swz128(row, c);
            size_t go = qbase + (size_t)row * NDH + c * 8;
            cpa16(sb + AQ_H + o, g_Qh + go);
            cpa16(sb + AQ_L + o, g_Ql + go);
        }
        CP_COMMIT();
    }

    // K/V stage issue
    const int rKV = tid >> 3, cKV = tid & 7;   // rows 0..15 base
    auto issue_kv = [&](int kt) {
        const uint32_t base = sb + ASTG_BASE + (kt & 1) * ASTG;
        #pragma unroll
        for (int j = 0; j < 4; j++) {
            int row = rKV + j * 16;
            uint32_t o = swz128(row, cKV);
            size_t go = kvbase + (size_t)(kt * 64 + row) * NDH + cKV * 8;
            cpa16(base + o,         g_Kh + go);
            cpa16(base + 8192  + o, g_Kl + go);
            cpa16(base + 16384 + o, g_Vh + go);
            cpa16(base + 24576 + o, g_Vl + go);
        }
    };
    issue_kv(0); CP_COMMIT();

    // ---- fragment smem offsets --------------------------------------------
    uint32_t qOff[4][2];
    #pragma unroll
    for (int kc = 0; kc < 4; kc++)
        #pragma unroll
        for (int mt = 0; mt < 2; mt++) {
            int r = warp * 32 + mt * 16 + (lane & 15);
            int c = kc * 2 + ((lane >> 4) & 1);
            qOff[kc][mt] = swz128(r, c);
        }
    uint32_t kOff[4][4];
    #pragma unroll
    for (int kc = 0; kc < 4; kc++)
        #pragma unroll
        for (int ntp = 0; ntp < 4; ntp++) {
            int r = ntp * 16 + (lane & 7) + ((lane >> 4) & 1) * 8;
            int c = kc * 2 + ((lane >> 3) & 1);
            kOff[kc][ntp] = swz128(r, c);
        }
    uint32_t vOff[4][4];
    #pragma unroll
    for (int kq = 0; kq < 4; kq++)
        #pragma unroll
        for (int dp = 0; dp < 4; dp++) {
            int r = kq * 16 + (lane & 7) + ((lane >> 3) & 1) * 8;
            int c = dp * 2 + ((lane >> 4) & 1);
            vOff[kq][dp] = swz128(r, c);
        }

    float Oa[2][8][4];
    float mrun[2][2], lrun[2][2];
    #pragma unroll
    for (int mt = 0; mt < 2; mt++) {
        mrun[mt][0] = -INFINITY; mrun[mt][1] = -INFINITY;
        lrun[mt][0] = 0.f;       lrun[mt][1] = 0.f;
        #pragma unroll
        for (int dt = 0; dt < 8; dt++)
            #pragma unroll
            for (int i = 0; i < 4; i++) Oa[mt][dt][i] = 0.f;
    }

    for (int kt = 0; kt < NS / 64; kt++) {
        CP_WAIT(0);
        __syncthreads();
        if (kt + 1 < NS / 64) issue_kv(kt + 1);
        CP_COMMIT();

        const uint32_t kb = sb + ASTG_BASE + (kt & 1) * ASTG;

        // ---- S = Q K^T (3-term) -------------------------------------------
        float S[2][8][4];
        #pragma unroll
        for (int mt = 0; mt < 2; mt++)
            #pragma unroll
            for (int nt = 0; nt < 8; nt++)
                #pragma unroll
                for (int i = 0; i < 4; i++) S[mt][nt][i] = 0.f;

        #pragma unroll
        for (int kc = 0; kc < 4; kc++) {
            uint32_t qh[2][4], ql[2][4];
            #pragma unroll
            for (int mt = 0; mt < 2; mt++) {
                ldmx4(sb + AQ_H + qOff[kc][mt], qh[mt]);
                ldmx4(sb + AQ_L + qOff[kc][mt], ql[mt]);
            }
            #pragma unroll
            for (int ntp = 0; ntp < 4; ntp++) {
                uint32_t kh[4], kl[4];
                ldmx4(kb + kOff[kc][ntp], kh);
                ldmx4(kb + 8192 + kOff[kc][ntp], kl);
                #pragma unroll
                for (int mt = 0; mt < 2; mt++) {
                    mma16816(S[mt][2*ntp],   qh[mt], kh[0], kh[1]);
                    mma16816(S[mt][2*ntp+1], qh[mt], kh[2], kh[3]);
                    mma16816(S[mt][2*ntp],   qh[mt], kl[0], kl[1]);
                    mma16816(S[mt][2*ntp+1], qh[mt], kl[2], kl[3]);
                    mma16816(S[mt][2*ntp],   ql[mt], kh[0], kh[1]);
                    mma16816(S[mt][2*ntp+1], ql[mt], kh[2], kh[3]);
                }
            }
        }

        // ---- online softmax -----------------------------------------------
        #pragma unroll
        for (int mt = 0; mt < 2; mt++) {
            float mx0 = -INFINITY, mx1 = -INFINITY;
            #pragma unroll
            for (int j = 0; j < 8; j++) {
                mx0 = fmaxf(mx0, fmaxf(S[mt][j][0], S[mt][j][1]));
                mx1 = fmaxf(mx1, fmaxf(S[mt][j][2], S[mt][j][3]));
            }
            mx0 = fmaxf(mx0, __shfl_xor_sync(0xffffffffu, mx0, 1));
            mx0 = fmaxf(mx0, __shfl_xor_sync(0xffffffffu, mx0, 2));
            mx1 = fmaxf(mx1, __shfl_xor_sync(0xffffffffu, mx1, 1));
            mx1 = fmaxf(mx1, __shfl_xor_sync(0xffffffffu, mx1, 2));
            float nm0 = fmaxf(mrun[mt][0], mx0);
            float nm1 = fmaxf(mrun[mt][1], mx1);
            float a0 = __expf(mrun[mt][0] - nm0);
            float a1 = __expf(mrun[mt][1] - nm1);
            mrun[mt][0] = nm0; mrun[mt][1] = nm1;
            float s0 = 0.f, s1 = 0.f;
            #pragma unroll
            for (int j = 0; j < 8; j++) {
                S[mt][j][0] = __expf(S[mt][j][0] - nm0); s0 += S[mt][j][0];
                S[mt][j][1] = __expf(S[mt][j][1] - nm0); s0 += S[mt][j][1];
                S[mt][j][2] = __expf(S[mt][j][2] - nm1); s1 += S[mt][j][2];
                S[mt][j][3] = __expf(S[mt][j][3] - nm1); s1 += S[mt][j][3];
            }
            s0 += __shfl_xor_sync(0xffffffffu, s0, 1);
            s0 += __shfl_xor_sync(0xffffffffu, s0, 2);
            s1 += __shfl_xor_sync(0xffffffffu, s1, 1);
            s1 += __shfl_xor_sync(0xffffffffu, s1, 2);
            lrun[mt][0] = lrun[mt][0] * a0 + s0;
            lrun[mt][1] = lrun[mt][1] * a1 + s1;
            #pragma unroll
            for (int dt = 0; dt < 8; dt++) {
                Oa[mt][dt][0] *= a0; Oa[mt][dt][1] *= a0;
                Oa[mt][dt][2] *= a1; Oa[mt][dt][3] *= a1;
            }
        }

        // ---- O += P V (3-term) --------------------------------------------
        #pragma unroll
        for (int kq = 0; kq < 4; kq++) {
            uint32_t pah[2][4], pal[2][4];
            #pragma unroll
            for (int mt = 0; mt < 2; mt++) {
                split2(S[mt][2*kq][0],   S[mt][2*kq][1],   pah[mt][0], pal[mt][0]);
                split2(S[mt][2*kq][2],   S[mt][2*kq][3],   pah[mt][1], pal[mt][1]);
                split2(S[mt][2*kq+1][0], S[mt][2*kq+1][1], pah[mt][2], pal[mt][2]);
                split2(S[mt][2*kq+1][2], S[mt][2*kq+1][3], pah[mt][3], pal[mt][3]);
            }
            #pragma unroll
            for (int dp = 0; dp < 4; dp++) {
                uint32_t vh[4], vl[4];
                ldmx4t(kb + 16384 + vOff[kq][dp], vh);
                ldmx4t(kb + 24576 + vOff[kq][dp], vl);
                #pragma unroll
                for (int mt = 0; mt < 2; mt++) {
                    mma16816(Oa[mt][2*dp],   pah[mt], vh[0], vh[1]);
                    mma16816(Oa[mt][2*dp+1], pah[mt], vh[2], vh[3]);
                    mma16816(Oa[mt][2*dp],   pah[mt], vl[0], vl[1]);
                    mma16816(Oa[mt][2*dp+1], pah[mt], vl[2], vl[3]);
                    mma16816(Oa[mt][2*dp],   pal[mt], vh[0], vh[1]);
                    mma16816(Oa[mt][2*dp+1], pal[mt], vh[2], vh[3]);
                }
            }
        }
    }

    // ---- epilogue: O /= l -> ctx hi/lo bf16 [B,S,H*Dh] --------------------
    const int b = bh >> 4, h = bh & 15;
    const int g = lane >> 2, tg = lane & 3;
    #pragma unroll
    for (int mt = 0; mt < 2; mt++)
        #pragma unroll
        for (int half = 0; half < 2; half++) {
            int q = qt * 128 + warp * 32 + mt * 16 + g + half * 8;
            float inv = 1.0f / lrun[mt][half];
            size_t rb = ((size_t)b * NS + q) * ND + h * NDH;
            #pragma unroll
            for (int dt = 0; dt < 8; dt++) {
                float vx = Oa[mt][dt][half*2]   * inv;
                float vy = Oa[mt][dt][half*2+1] * inv;
                uint32_t hi, lo;
                split2(vx, vy, hi, lo);
                size_t o = rb + dt * 8 + tg * 2;
                *(uint32_t*)((char*)g_ctxh + o * 2) = hi;
                *(uint32_t*)((char*)g_ctxl + o * 2) = lo;
            }
        }
}

// ===========================================================================
extern "C" void kernel_launch(void* const* d_in, const int* in_sizes, int n_in,
                              void* d_out, int out_size)
{
    (void)in_sizes; (void)n_in; (void)out_size;
    const float* x      = (const float*)d_in[0];
    const int*   p      = (const int*)d_in[1];
    const float* Wqkv_w = (const float*)d_in[2];
    const float* Wqkv_b = (const float*)d_in[3];
    const float* Wo_w   = (const float*)d_in[4];
    const float* Wo_b   = (const float*)d_in[5];
    float* out = (float*)d_out;

    cudaFuncSetAttribute(gemm_bf16<0>,
                         cudaFuncAttributeMaxDynamicSharedMemorySize, GK_SMEM);
    cudaFuncSetAttribute(gemm_bf16<1>,
                         cudaFuncAttributeMaxDynamicSharedMemorySize, GK_SMEM);
    cudaFuncSetAttribute(attn_mma,
                         cudaFuncAttributeMaxDynamicSharedMemorySize, AT_SMEM);

    // resolve device-global addresses (host side, graph-capturable)
    __nv_bfloat16 *xh, *xl, *wqh, *wql, *woh, *wol, *ctxh, *ctxl;
    cudaGetSymbolAddress((void**)&xh,  g_xh);  cudaGetSymbolAddress((void**)&xl,  g_xl);
    cudaGetSymbolAddress((void**)&wqh, g_wqh); cudaGetSymbolAddress((void**)&wql, g_wql);
    cudaGetSymbolAddress((void**)&woh, g_woh); cudaGetSymbolAddress((void**)&wol, g_wol);
    cudaGetSymbolAddress((void**)&ctxh, g_ctxh); cudaGetSymbolAddress((void**)&ctxl, g_ctxl);

    // 0) split inputs to bf16 hi/lo
    int n4x = MT * ND / 4, n4wq = 3 * ND * ND / 4, n4wo = ND * ND / 4;
    conv_split<<<(n4x  + 255) / 256, 256>>>((const float4*)x,      (uint2*)xh,  (uint2*)xl,  n4x);
    conv_split<<<(n4wq + 255) / 256, 256>>>((const float4*)Wqkv_w, (uint2*)wqh, (uint2*)wql, n4wq);
    conv_split<<<(n4wo + 255) / 256, 256>>>((const float4*)Wo_w,   (uint2*)woh, (uint2*)wol, n4wo);

    // 1) QKV projection
    dim3 g1(3 * ND / 128, MT / 128);
    gemm_bf16<0><<<g1, 256, GK_SMEM>>>(xh, xl, wqh, wql, Wqkv_b, nullptr, 3 * ND, ND);

    // 2) RoPE + split
    int nrope = NB * NH * NS * 32;
    rope_split<<<(nrope + 255) / 256, 256>>>(p);

    // 3) Attention
    attn_mma<<<dim3(NS / 128, NB * NH), 128, AT_SMEM>>>();

    // 4) Output projection
    dim3 g2(ND / 128, MT / 128);
    gemm_bf16<1><<<g2, 256, GK_SMEM>>>(ctxh, ctxl, woh, wol, Wo_b, out, ND, ND);
}